// round 6
// baseline (speedup 1.0000x reference)
#include <cuda_runtime.h>
#include <cstdint>

#define SMALL_VAL (-1000.0f)
#define NSM 148

// Allocation-free scratch.
__device__ float g_partials[8192];
__device__ int   g_perm[8192];
__device__ int   g_done;          // zero-init; last block resets to 0 each run

// ---------- packed f32x2 helpers (Blackwell; ptxas won't auto-fuse) ----------
__device__ __forceinline__ unsigned long long pack2(float x, float y) {
    unsigned long long r;
    asm("mov.b64 %0, {%1, %2};" : "=l"(r) : "f"(x), "f"(y));
    return r;
}
__device__ __forceinline__ void unpack2(unsigned long long v, float& x, float& y) {
    asm("mov.b64 {%0, %1}, %2;" : "=f"(x), "=f"(y) : "l"(v));
}
__device__ __forceinline__ unsigned long long ffma2(unsigned long long a,
                                                    unsigned long long b,
                                                    unsigned long long c) {
    unsigned long long d;
    asm("fma.rn.f32x2 %0, %1, %2, %3;" : "=l"(d) : "l"(a), "l"(b), "l"(c));
    return d;
}
__device__ __forceinline__ unsigned long long fmul2(unsigned long long a,
                                                    unsigned long long b) {
    unsigned long long d;
    asm("mul.rn.f32x2 %0, %1, %2;" : "=l"(d) : "l"(a), "l"(b));
    return d;
}
__device__ __forceinline__ unsigned long long fadd2(unsigned long long a,
                                                    unsigned long long b) {
    unsigned long long d;
    asm("add.rn.f32x2 %0, %1, %2;" : "=l"(d) : "l"(a), "l"(b));
    return d;
}

// ============================================================================
// Load-balancing permutation (parallel across blocks): rank batches by
// seq_len (desc, stable), snake-assign ranks over rows of NSM. The perm only
// changes scheduling; g_partials is indexed by batch and reduced in fixed
// order, so the output value is independent of the perm.
// ============================================================================
__global__ void crf_perm_kernel(const int* __restrict__ seq_len, int B)
{
    __shared__ int ns[4096];
    const bool use_sh = (B <= 4096);
    if (use_sh) {
        for (int i = threadIdx.x; i < B; i += blockDim.x) ns[i] = seq_len[i];
        __syncthreads();
    }
    int i = blockIdx.x * blockDim.x + threadIdx.x;
    if (i >= B) return;
    int ni = use_sh ? ns[i] : seq_len[i];
    int r = 0;
    #pragma unroll 4
    for (int j = 0; j < B; j++) {
        int nj = use_sh ? ns[j] : seq_len[j];
        r += (nj > ni) || (nj == ni && j < i);
    }
    int row   = r / NSM;
    int base  = row * NSM;
    int width = min(NSM, B - base);
    int col   = r - base;
    int c     = ((row & 1) && width == NSM) ? (NSM - 1 - col) : col;
    g_perm[base + c] = i;
}

// ============================================================================
// Forward CRF: one block (128 threads, 4 warps) per batch element.
// Thread pair (2c, 2c+1) owns output column c; halves k in [0,32)/[32,64).
//
// Linear-domain recursion:
//   a_t[k'] = (sum_k a_{t-1}[k] * E[k][k']) * exp(obs_t[k']) * 2^{-e_t}
// E = exp(transitions), half-column in registers (16 packed f32x2; k=62,63
// entries are exp(-10000)=0, no special case needed). a double-buffered in
// shared (one BAR/step). Rescale exponent from a_prev[0] (lane-uniform on
// even threads, exact pow2) accumulated as integer, folded in as etot*ln2.
// Step 1 in exact log domain. pred rows software-prefetched 8 steps ahead.
// Last-finishing block does the deterministic fixed-order final reduction.
// ============================================================================
__global__ void __launch_bounds__(128, 6) crf_forward_kernel(
    const float* __restrict__ pred,
    const int*   __restrict__ ref,
    const int*   __restrict__ seq_len,
    const float* __restrict__ trans,
    float* __restrict__ out,
    int B, int T, int L)
{
    __shared__ float Tsh[64 * 64];
    __shared__ __align__(16) float abuf[2][64];
    __shared__ float red[128];
    __shared__ float s_res;
    __shared__ int   s_last;

    const int b   = g_perm[blockIdx.x];
    const int tid = threadIdx.x;
    const int h   = tid & 1;             // k-half
    const int c   = tid >> 1;            // output column 0..63
    const int n   = seq_len[b];          // in [1, T]
    const size_t bT = (size_t)b * T;
    const bool loader = (h == 0) && (c < L);   // threads that stream pred

    // ---- load transitions (K = L+2 = 64) ----
    for (int i = tid; i < 64 * 64; i += 128) Tsh[i] = trans[i];
    __syncthreads();

    // ---- E half-column: k = h*32 + [0,32), output column c ----
    unsigned long long Ereg[16];
    #pragma unroll
    for (int i = 0; i < 16; i++) {
        int k0 = h * 32 + 2 * i;
        float e0 = __expf(Tsh[k0 * 64 + c]);
        float e1 = __expf(Tsh[(k0 + 1) * 64 + c]);
        Ereg[i] = pack2(e0, e1);
    }

    // ---- step 1 (obs row 1 = pred row 0), exact log-domain LSE ----
    float alpha1 = 0.0f;
    if (h == 0) {
        float obs1 = (c < L) ? pred[(bT + 0) * L + c] : SMALL_VAL;
        float m = -3.4e38f;
        #pragma unroll 8
        for (int k = 0; k < 64; k++) {
            float init = (k == L) ? 0.0f : SMALL_VAL;   // b_s
            m = fmaxf(m, init + Tsh[k * 64 + c]);
        }
        float se = 0.0f;
        #pragma unroll 8
        for (int k = 0; k < 64; k++) {
            float init = (k == L) ? 0.0f : SMALL_VAL;
            se += __expf(init + Tsh[k * 64 + c] - m);
        }
        alpha1 = obs1 + m + __logf(se);
        abuf[0][c] = alpha1;
    }
    __syncthreads();
    float m1 = -3.4e38f;
    #pragma unroll 8
    for (int k = 0; k < 64; k++) m1 = fmaxf(m1, abuf[0][k]);
    __syncthreads();
    if (h == 0) abuf[0][c] = __expf(alpha1 - m1);   // linear a_1
    __syncthreads();

    // ---- main loop: S = n-1 steps; step q consumes pred row q+1 ----
    const int S = n - 1;
    int etot = 0;
    int cur  = 0;

    // 8-deep register prefetch pipeline (loader threads hold pred column c).
    float buf[8];
    #pragma unroll
    for (int j = 0; j < 8; j++) {
        buf[j] = (loader && j < S) ? pred[(bT + 1 + j) * L + c] : SMALL_VAL;
    }

    auto step_body = [&](int q, int j) {
        // P only meaningful on h==0 threads; odd threads' value is dead.
        float P = (h == 0) ? __expf(buf[j]) : 0.0f;
        int row = q + 9;
        float nf = SMALL_VAL;
        if (loader && row <= S) nf = pred[(bT + row) * L + c];

        // this thread's a-half: 8 x LDS.128
        const ulonglong2* a2 = (const ulonglong2*)(&abuf[cur][h * 32]);
        ulonglong2 v0 = a2[0];
        // rescale from a_prev[0] exponent (valid on even threads)
        int e = ((int)(v0.x >> 23) & 255) - 127;
        e = max(-60, min(60, e));
        float ps = P * __int_as_float((127 - e) << 23);   // P * 2^{-e}

        unsigned long long acc[8];
        acc[0] = fmul2(v0.x, Ereg[0]);
        acc[1] = fmul2(v0.y, Ereg[1]);
        #pragma unroll
        for (int q4 = 1; q4 < 4; q4++) {
            ulonglong2 v = a2[q4];
            acc[2 * q4]     = fmul2(v.x, Ereg[2 * q4]);
            acc[2 * q4 + 1] = fmul2(v.y, Ereg[2 * q4 + 1]);
        }
        #pragma unroll
        for (int q4 = 4; q4 < 8; q4++) {
            ulonglong2 v = a2[q4];
            acc[(2 * q4) & 7]     = ffma2(v.x, Ereg[2 * q4], acc[(2 * q4) & 7]);
            acc[(2 * q4 + 1) & 7] = ffma2(v.y, Ereg[2 * q4 + 1], acc[(2 * q4 + 1) & 7]);
        }
        unsigned long long sfin =
            fadd2(fadd2(fadd2(acc[0], acc[1]), fadd2(acc[2], acc[3])),
                  fadd2(fadd2(acc[4], acc[5]), fadd2(acc[6], acc[7])));
        float sx, sy; unpack2(sfin, sx, sy);
        float sh_ = sx + sy;
        float s = sh_ + __shfl_xor_sync(0xffffffffu, sh_, 1);   // combine halves

        if (h == 0) abuf[cur ^ 1][c] = s * ps;
        etot += e;
        buf[j] = nf;
        cur ^= 1;
        __syncthreads();
    };

    const int full = S & ~7;
    for (int s0 = 0; s0 < full; s0 += 8) {
        #pragma unroll
        for (int j = 0; j < 8; j++) step_body(s0 + j, j);
    }
    #pragma unroll
    for (int j = 0; j < 8; j++) {       // remainder; guards block-uniform
        if (full + j < S) step_body(full + j, j);
    }

    // ---- final step (obs row n+1): only end column (c==63) matters ----
    {
        const ulonglong2* a2 = (const ulonglong2*)(&abuf[cur][h * 32]);
        unsigned long long acc[8];
        #pragma unroll
        for (int q4 = 0; q4 < 4; q4++) {
            ulonglong2 v = a2[q4];
            acc[2 * q4]     = fmul2(v.x, Ereg[2 * q4]);
            acc[2 * q4 + 1] = fmul2(v.y, Ereg[2 * q4 + 1]);
        }
        #pragma unroll
        for (int q4 = 4; q4 < 8; q4++) {
            ulonglong2 v = a2[q4];
            acc[(2 * q4) & 7]     = ffma2(v.x, Ereg[2 * q4], acc[(2 * q4) & 7]);
            acc[(2 * q4 + 1) & 7] = ffma2(v.y, Ereg[2 * q4 + 1], acc[(2 * q4 + 1) & 7]);
        }
        unsigned long long sfin =
            fadd2(fadd2(fadd2(acc[0], acc[1]), fadd2(acc[2], acc[3])),
                  fadd2(fadd2(acc[4], acc[5]), fadd2(acc[6], acc[7])));
        float sx, sy; unpack2(sfin, sx, sy);
        float sh_ = sx + sy;
        float s = sh_ + __shfl_xor_sync(0xffffffffu, sh_, 1);
        if (tid == 126) {   // h==0 owner of column 63 (= end state)
            s_res = m1 + (float)etot * 0.6931471805599453f + __logf(s);
        }
    }

    // ---- gold path score: 2-phase loads for MLP (ref first, then gathers) ----
    int   rr[4], rp[4];
    float gv[4];
    #pragma unroll
    for (int u = 0; u < 4; u++) {
        int t = tid + u * 128;
        rr[u] = (t < n) ? ref[bT + t] : 0;
        rp[u] = (t >= 1 && t < n) ? ref[bT + t - 1] : 0;
    }
    #pragma unroll
    for (int u = 0; u < 4; u++) {
        int t = tid + u * 128;
        gv[u] = (t < n) ? pred[(bT + t) * L + rr[u]] : 0.0f;
    }
    float rs = 0.0f;
    #pragma unroll
    for (int u = 0; u < 4; u++) {
        int t = tid + u * 128;
        if (t < n) {
            rs += gv[u];
            if (t >= 1) rs += Tsh[rp[u] * 64 + rr[u]];
        }
    }
    // general fallback for T > 512 (no-op for this problem size)
    for (int t = tid + 512; t < n; t += 128) {
        int r = ref[bT + t];
        rs += pred[(bT + t) * L + r] + Tsh[ref[bT + t - 1] * 64 + r];
    }
    if (tid == 0) {
        int r0 = ref[bT + 0];
        int rl = ref[bT + n - 1];
        rs += Tsh[L * 64 + r0];          // start -> ref[0]
        rs += Tsh[rl * 64 + (L + 1)];    // ref[n-1] -> end
    }
    red[tid] = rs;
    __syncthreads();
    if (tid == 0) {
        float tot = 0.0f;
        #pragma unroll 8
        for (int k = 0; k < 128; k++) tot += red[k];   // fixed order
        g_partials[b] = s_res - tot;
    }

    // ---- last block does the deterministic fixed-order final reduction ----
    __threadfence();
    if (tid == 0) s_last = (atomicAdd(&g_done, 1) == (int)gridDim.x - 1);
    __syncthreads();
    if (s_last) {
        volatile float* gp = g_partials;
        float v = 0.0f;
        for (int i = tid; i < B; i += 128) v += gp[i];   // fixed order per lane
        red[tid] = v;
        __syncthreads();
        if (tid == 0) {
            float tot = 0.0f;
            #pragma unroll 8
            for (int k = 0; k < 128; k++) tot += red[k]; // fixed order
            out[0] = tot;
            g_done = 0;                                   // graph-replay reset
        }
    }
}

extern "C" void kernel_launch(void* const* d_in, const int* in_sizes, int n_in,
                              void* d_out, int out_size)
{
    const float* pred = (const float*)d_in[0];
    const int*   ref  = (const int*)d_in[1];
    const int*   seq  = (const int*)d_in[2];
    const float* trn  = (const float*)d_in[3];

    int B = in_sizes[2];                 // seq_len has B elements
    int T = in_sizes[1] / B;             // ref is B*T
    int L = in_sizes[0] / in_sizes[1];   // pred is B*T*L

    crf_perm_kernel<<<(B + 63) / 64, 64>>>(seq, B);
    crf_forward_kernel<<<B, 128>>>(pred, ref, seq, trn, (float*)d_out, B, T, L);
}

// round 7
// speedup vs baseline: 1.3578x; 1.3578x over previous
#include <cuda_runtime.h>
#include <cstdint>

#define SMALL_VAL (-1000.0f)
#define NSM 148

// Allocation-free scratch.
__device__ float g_partials[8192];
__device__ int   g_perm[8192];
__device__ int   g_done;          // zero-init; last block resets to 0 each run

// ---------- packed f32x2 helpers (Blackwell; ptxas won't auto-fuse) ----------
__device__ __forceinline__ unsigned long long pack2(float x, float y) {
    unsigned long long r;
    asm("mov.b64 %0, {%1, %2};" : "=l"(r) : "f"(x), "f"(y));
    return r;
}
__device__ __forceinline__ void unpack2(unsigned long long v, float& x, float& y) {
    asm("mov.b64 {%0, %1}, %2;" : "=f"(x), "=f"(y) : "l"(v));
}
__device__ __forceinline__ unsigned long long ffma2(unsigned long long a,
                                                    unsigned long long b,
                                                    unsigned long long c) {
    unsigned long long d;
    asm("fma.rn.f32x2 %0, %1, %2, %3;" : "=l"(d) : "l"(a), "l"(b), "l"(c));
    return d;
}
__device__ __forceinline__ unsigned long long fmul2(unsigned long long a,
                                                    unsigned long long b) {
    unsigned long long d;
    asm("mul.rn.f32x2 %0, %1, %2;" : "=l"(d) : "l"(a), "l"(b));
    return d;
}
__device__ __forceinline__ unsigned long long fadd2(unsigned long long a,
                                                    unsigned long long b) {
    unsigned long long d;
    asm("add.rn.f32x2 %0, %1, %2;" : "=l"(d) : "l"(a), "l"(b));
    return d;
}

// ============================================================================
// Load-balancing permutation (parallel across blocks): rank batches by
// seq_len (desc, stable), snake-assign ranks over rows of NSM. The perm only
// changes scheduling; g_partials is indexed by batch and reduced in fixed
// order, so the output value is independent of the perm.
// ============================================================================
__global__ void crf_perm_kernel(const int* __restrict__ seq_len, int B)
{
    __shared__ int ns[4096];
    const bool use_sh = (B <= 4096);
    if (use_sh) {
        for (int i = threadIdx.x; i < B; i += blockDim.x) ns[i] = seq_len[i];
        __syncthreads();
    }
    int i = blockIdx.x * blockDim.x + threadIdx.x;
    if (i >= B) return;
    int ni = use_sh ? ns[i] : seq_len[i];
    int r = 0;
    #pragma unroll 4
    for (int j = 0; j < B; j++) {
        int nj = use_sh ? ns[j] : seq_len[j];
        r += (nj > ni) || (nj == ni && j < i);
    }
    int row   = r / NSM;
    int base  = row * NSM;
    int width = min(NSM, B - base);
    int col   = r - base;
    int c     = ((row & 1) && width == NSM) ? (NSM - 1 - col) : col;
    g_perm[base + c] = i;
}

// ============================================================================
// Forward CRF: one block (128 threads, 4 warps) per batch element.
// Thread pair (2c, 2c+1) owns output column c; halves k in [0,32)/[32,64).
//
// a is stored split with a 4-bank skew: a[0..31] at float offs 0..31,
// a[32..63] at float offs 36..67 (base 144 B). The two per-warp broadcast
// addresses of each LDS.128 then hit DISJOINT bank quadruples (banks 4q..4q+3
// vs 4q+4..4q+7) -> conflict-free single wavefront. (Unpadded 128 B offset
// aliased to the same banks -> 2-way conflict, the R6 regression.)
//
// Linear-domain recursion:
//   a_t[k'] = (sum_k a_{t-1}[k] * E[k][k']) * exp(obs_t[k']) * 2^{-e_t}
// E = exp(transitions), half-column in registers (16 packed f32x2). Rescale
// exponent from a_prev[0] (even threads, exact pow2), accumulated as integer,
// folded in at the end as etot*ln2. Step 1 in exact log domain. pred rows
// software-prefetched 8 steps ahead. Last-finishing block reduces.
// ============================================================================
__global__ void __launch_bounds__(128, 6) crf_forward_kernel(
    const float* __restrict__ pred,
    const int*   __restrict__ ref,
    const int*   __restrict__ seq_len,
    const float* __restrict__ trans,
    float* __restrict__ out,
    int B, int T, int L)
{
    __shared__ float Tsh[64 * 64];
    __shared__ __align__(16) float abuf[2][72];   // halves at +0 / +36 floats
    __shared__ float red[128];
    __shared__ float s_res;
    __shared__ int   s_last;

    const int b   = g_perm[blockIdx.x];
    const int tid = threadIdx.x;
    const int h   = tid & 1;             // k-half
    const int c   = tid >> 1;            // output column 0..63
    const int cs  = c + ((c >> 5) << 2); // skewed store index for column c
    const int n   = seq_len[b];          // in [1, T]
    const size_t bT = (size_t)b * T;
    const bool loader = (h == 0) && (c < L);   // threads that stream pred

    // ---- load transitions (K = L+2 = 64) ----
    for (int i = tid; i < 64 * 64; i += 128) Tsh[i] = trans[i];
    __syncthreads();

    // ---- E half-column: k = h*32 + [0,32), output column c ----
    unsigned long long Ereg[16];
    #pragma unroll
    for (int i = 0; i < 16; i++) {
        int k0 = h * 32 + 2 * i;
        float e0 = __expf(Tsh[k0 * 64 + c]);
        float e1 = __expf(Tsh[(k0 + 1) * 64 + c]);
        Ereg[i] = pack2(e0, e1);
    }

    // ---- step 1 (obs row 1 = pred row 0), exact log-domain LSE ----
    float alpha1 = 0.0f;
    if (h == 0) {
        float obs1 = (c < L) ? pred[(bT + 0) * L + c] : SMALL_VAL;
        float m = -3.4e38f;
        #pragma unroll 8
        for (int k = 0; k < 64; k++) {
            float init = (k == L) ? 0.0f : SMALL_VAL;   // b_s
            m = fmaxf(m, init + Tsh[k * 64 + c]);
        }
        float se = 0.0f;
        #pragma unroll 8
        for (int k = 0; k < 64; k++) {
            float init = (k == L) ? 0.0f : SMALL_VAL;
            se += __expf(init + Tsh[k * 64 + c] - m);
        }
        alpha1 = obs1 + m + __logf(se);
        abuf[0][cs] = alpha1;
    }
    __syncthreads();
    float m1 = -3.4e38f;
    #pragma unroll 8
    for (int k = 0; k < 64; k++) m1 = fmaxf(m1, abuf[0][k + ((k >> 5) << 2)]);
    __syncthreads();
    if (h == 0) abuf[0][cs] = __expf(alpha1 - m1);   // linear a_1
    __syncthreads();

    // ---- main loop: S = n-1 steps; step q consumes pred row q+1 ----
    const int S = n - 1;
    int etot = 0;
    int cur  = 0;

    // 8-deep register prefetch pipeline (loader threads hold pred column c).
    float buf[8];
    #pragma unroll
    for (int j = 0; j < 8; j++) {
        buf[j] = (loader && j < S) ? pred[(bT + 1 + j) * L + c] : SMALL_VAL;
    }

    auto step_body = [&](int q, int j) {
        // P only meaningful on h==0 threads; odd threads' value is dead.
        float P = (h == 0) ? __expf(buf[j]) : 0.0f;
        int row = q + 9;
        float nf = SMALL_VAL;
        if (loader && row <= S) nf = pred[(bT + row) * L + c];

        // this thread's a-half: 8 x LDS.128, bank-skewed base (conflict-free)
        const ulonglong2* a2 = (const ulonglong2*)(&abuf[cur][h * 36]);
        ulonglong2 v0 = a2[0];
        // rescale from a_prev[0] exponent (valid on even threads)
        int e = ((int)(v0.x >> 23) & 255) - 127;
        e = max(-60, min(60, e));
        float ps = P * __int_as_float((127 - e) << 23);   // P * 2^{-e}

        unsigned long long acc[8];
        acc[0] = fmul2(v0.x, Ereg[0]);
        acc[1] = fmul2(v0.y, Ereg[1]);
        #pragma unroll
        for (int q4 = 1; q4 < 4; q4++) {
            ulonglong2 v = a2[q4];
            acc[2 * q4]     = fmul2(v.x, Ereg[2 * q4]);
            acc[2 * q4 + 1] = fmul2(v.y, Ereg[2 * q4 + 1]);
        }
        #pragma unroll
        for (int q4 = 4; q4 < 8; q4++) {
            ulonglong2 v = a2[q4];
            acc[(2 * q4) & 7]     = ffma2(v.x, Ereg[2 * q4], acc[(2 * q4) & 7]);
            acc[(2 * q4 + 1) & 7] = ffma2(v.y, Ereg[2 * q4 + 1], acc[(2 * q4 + 1) & 7]);
        }
        unsigned long long sfin =
            fadd2(fadd2(fadd2(acc[0], acc[1]), fadd2(acc[2], acc[3])),
                  fadd2(fadd2(acc[4], acc[5]), fadd2(acc[6], acc[7])));
        float sx, sy; unpack2(sfin, sx, sy);
        float sh_ = sx + sy;
        float s = sh_ + __shfl_xor_sync(0xffffffffu, sh_, 1);   // combine halves

        if (h == 0) abuf[cur ^ 1][cs] = s * ps;
        etot += e;
        buf[j] = nf;
        cur ^= 1;
        __syncthreads();
    };

    const int full = S & ~7;
    for (int s0 = 0; s0 < full; s0 += 8) {
        #pragma unroll
        for (int j = 0; j < 8; j++) step_body(s0 + j, j);
    }
    #pragma unroll
    for (int j = 0; j < 8; j++) {       // remainder; guards block-uniform
        if (full + j < S) step_body(full + j, j);
    }

    // ---- final step (obs row n+1): only end column (c==63) matters ----
    {
        const ulonglong2* a2 = (const ulonglong2*)(&abuf[cur][h * 36]);
        unsigned long long acc[8];
        #pragma unroll
        for (int q4 = 0; q4 < 4; q4++) {
            ulonglong2 v = a2[q4];
            acc[2 * q4]     = fmul2(v.x, Ereg[2 * q4]);
            acc[2 * q4 + 1] = fmul2(v.y, Ereg[2 * q4 + 1]);
        }
        #pragma unroll
        for (int q4 = 4; q4 < 8; q4++) {
            ulonglong2 v = a2[q4];
            acc[(2 * q4) & 7]     = ffma2(v.x, Ereg[2 * q4], acc[(2 * q4) & 7]);
            acc[(2 * q4 + 1) & 7] = ffma2(v.y, Ereg[2 * q4 + 1], acc[(2 * q4 + 1) & 7]);
        }
        unsigned long long sfin =
            fadd2(fadd2(fadd2(acc[0], acc[1]), fadd2(acc[2], acc[3])),
                  fadd2(fadd2(acc[4], acc[5]), fadd2(acc[6], acc[7])));
        float sx, sy; unpack2(sfin, sx, sy);
        float sh_ = sx + sy;
        float s = sh_ + __shfl_xor_sync(0xffffffffu, sh_, 1);
        if (tid == 126) {   // h==0 owner of column 63 (= end state)
            s_res = m1 + (float)etot * 0.6931471805599453f + __logf(s);
        }
    }

    // ---- gold path score: 2-phase loads for MLP (ref first, then gathers) ----
    int   rr[4], rp[4];
    float gv[4];
    #pragma unroll
    for (int u = 0; u < 4; u++) {
        int t = tid + u * 128;
        rr[u] = (t < n) ? ref[bT + t] : 0;
        rp[u] = (t >= 1 && t < n) ? ref[bT + t - 1] : 0;
    }
    #pragma unroll
    for (int u = 0; u < 4; u++) {
        int t = tid + u * 128;
        gv[u] = (t < n) ? pred[(bT + t) * L + rr[u]] : 0.0f;
    }
    float rs = 0.0f;
    #pragma unroll
    for (int u = 0; u < 4; u++) {
        int t = tid + u * 128;
        if (t < n) {
            rs += gv[u];
            if (t >= 1) rs += Tsh[rp[u] * 64 + rr[u]];
        }
    }
    // general fallback for T > 512 (no-op for this problem size)
    for (int t = tid + 512; t < n; t += 128) {
        int r = ref[bT + t];
        rs += pred[(bT + t) * L + r] + Tsh[ref[bT + t - 1] * 64 + r];
    }
    if (tid == 0) {
        int r0 = ref[bT + 0];
        int rl = ref[bT + n - 1];
        rs += Tsh[L * 64 + r0];          // start -> ref[0]
        rs += Tsh[rl * 64 + (L + 1)];    // ref[n-1] -> end
    }
    red[tid] = rs;
    __syncthreads();
    if (tid == 0) {
        float tot = 0.0f;
        #pragma unroll 8
        for (int k = 0; k < 128; k++) tot += red[k];   // fixed order
        g_partials[b] = s_res - tot;
    }

    // ---- last block does the deterministic fixed-order final reduction ----
    __threadfence();
    if (tid == 0) s_last = (atomicAdd(&g_done, 1) == (int)gridDim.x - 1);
    __syncthreads();
    if (s_last) {
        volatile float* gp = g_partials;
        float v = 0.0f;
        for (int i = tid; i < B; i += 128) v += gp[i];   // fixed order per lane
        red[tid] = v;
        __syncthreads();
        if (tid == 0) {
            float tot = 0.0f;
            #pragma unroll 8
            for (int k = 0; k < 128; k++) tot += red[k]; // fixed order
            out[0] = tot;
            g_done = 0;                                   // graph-replay reset
        }
    }
}

extern "C" void kernel_launch(void* const* d_in, const int* in_sizes, int n_in,
                              void* d_out, int out_size)
{
    const float* pred = (const float*)d_in[0];
    const int*   ref  = (const int*)d_in[1];
    const int*   seq  = (const int*)d_in[2];
    const float* trn  = (const float*)d_in[3];

    int B = in_sizes[2];                 // seq_len has B elements
    int T = in_sizes[1] / B;             // ref is B*T
    int L = in_sizes[0] / in_sizes[1];   // pred is B*T*L

    crf_perm_kernel<<<(B + 63) / 64, 64>>>(seq, B);
    crf_forward_kernel<<<B, 128>>>(pred, ref, seq, trn, (float*)d_out, B, T, L);
}

// round 9
// speedup vs baseline: 1.4187x; 1.0448x over previous
#include <cuda_runtime.h>
#include <cstdint>

#define SMALL_VAL (-1000.0f)
#define FULLM 0xffffffffu

// Allocation-free scratch.
__device__ float g_partials[8192];
__device__ int   g_perm[8192];
__device__ int   g_done;          // zero-init; last warp resets to 0 each run

// ---------- packed f32x2 helpers (Blackwell; ptxas won't auto-fuse) ----------
__device__ __forceinline__ unsigned long long pack2(float x, float y) {
    unsigned long long r;
    asm("mov.b64 %0, {%1, %2};" : "=l"(r) : "f"(x), "f"(y));
    return r;
}
__device__ __forceinline__ void unpack2(unsigned long long v, float& x, float& y) {
    asm("mov.b64 {%0, %1}, %2;" : "=f"(x), "=f"(y) : "l"(v));
}
__device__ __forceinline__ unsigned long long ffma2(unsigned long long a,
                                                    unsigned long long b,
                                                    unsigned long long c) {
    unsigned long long d;
    asm("fma.rn.f32x2 %0, %1, %2, %3;" : "=l"(d) : "l"(a), "l"(b), "l"(c));
    return d;
}
__device__ __forceinline__ unsigned long long fmul2(unsigned long long a,
                                                    unsigned long long b) {
    unsigned long long d;
    asm("mul.rn.f32x2 %0, %1, %2;" : "=l"(d) : "l"(a), "l"(b));
    return d;
}
__device__ __forceinline__ unsigned long long fadd2(unsigned long long a,
                                                    unsigned long long b) {
    unsigned long long d;
    asm("add.rn.f32x2 %0, %1, %2;" : "=l"(d) : "l"(a), "l"(b));
    return d;
}

// ============================================================================
// Scheduling permutation: rank batches by seq_len descending (stable).
// Block k's 4 warps take ranks 4k..4k+3 -> near-equal lengths within a block
// (minimal intra-block straggle), longest blocks scheduled first (LPT).
// Scheduling only; the reduced value is order-independent by construction.
// ============================================================================
__global__ void crf_perm_kernel(const int* __restrict__ seq_len, int B)
{
    __shared__ int ns[4096];
    const bool use_sh = (B <= 4096);
    if (use_sh) {
        for (int i = threadIdx.x; i < B; i += blockDim.x) ns[i] = seq_len[i];
        __syncthreads();
    }
    int i = blockIdx.x * blockDim.x + threadIdx.x;
    if (i >= B) return;
    int ni = use_sh ? ns[i] : seq_len[i];
    int r = 0;
    #pragma unroll 4
    for (int j = 0; j < B; j++) {
        int nj = use_sh ? ns[j] : seq_len[j];
        r += (nj > ni) || (nj == ni && j < i);
    }
    g_perm[r] = i;
}

// ============================================================================
// Forward CRF: 128-thread blocks = 4 INDEPENDENT warps, each one batch
// element (warp w of block k handles g_perm[4k+w]). Warps occupy SMSPs 0..3
// by wid%4 -> guaranteed scheduler spread. After the shared transitions load
// (one __syncthreads), warps never sync with each other.
//
// Per warp, lane l owns columns c0 = l, c1 = l + 32.
// Linear-domain recursion:
//   a_t[k'] = (sum_k a_{t-1}[k] * E[k][k']) * exp(obs_t[k']) * 2^{-e_t}
// E = exp(transitions): 2 columns x 32 packed f32x2 in registers (rows 62/63
// are exp(-10000) = 0 automatically). a double-buffered per warp in shared,
// read as 16 broadcast LDS.128 per step shared by both columns ->
// 64 ffma2 per ~110 warp-instructions. Rescale exponent from a_prev[0]
// (uniform), exact integer accumulation, folded in at the end as etot*ln2.
// Step 1 in exact log domain. pred rows software-prefetched 8 steps ahead.
// Last-finishing warp does the deterministic final reduction.
// ============================================================================
__global__ void __launch_bounds__(128, 2) crf_forward_kernel(
    const float* __restrict__ pred,
    const int*   __restrict__ ref,
    const int*   __restrict__ seq_len,
    const float* __restrict__ trans,
    float* __restrict__ out,
    int B, int T, int L)
{
    __shared__ float Tsh[64 * 64];
    __shared__ __align__(16) float abuf[4][2][64];   // per-warp double buffer

    const int w  = threadIdx.x >> 5;     // warp in block = SMSP
    const int l  = threadIdx.x & 31;
    const int gw = blockIdx.x * 4 + w;   // global warp index = rank
    const int c0 = l;                    // always < L (= 62)
    const int c1 = l + 32;               // 32..63; end state = 63
    const int nwarp = (B + 3) / 4 * 4;   // padded warp count (B multiple of 4 here)

    // ---- load transitions (K = L+2 = 64) cooperatively, one block sync ----
    {
        const float4* src = (const float4*)trans;
        float4* dst = (float4*)Tsh;
        for (int i = threadIdx.x; i < 1024; i += 128) dst[i] = src[i];
    }
    __syncthreads();

    const bool active = (gw < B);
    const int b = active ? g_perm[gw] : 0;
    const int n = active ? seq_len[b] : 1;     // in [1, T]
    const size_t bT = (size_t)b * T;

    // ---- E columns c0, c1 in registers (32 k-pairs each) ----
    unsigned long long E0[32], E1[32];
    #pragma unroll
    for (int p = 0; p < 32; p++) {
        E0[p] = pack2(__expf(Tsh[(2 * p) * 64 + c0]),
                      __expf(Tsh[(2 * p + 1) * 64 + c0]));
        E1[p] = pack2(__expf(Tsh[(2 * p) * 64 + c1]),
                      __expf(Tsh[(2 * p + 1) * 64 + c1]));
    }

    // ---- step 1 (obs row 1 = pred row 0), exact log-domain LSE ----
    float obsA = active ? pred[(bT + 0) * L + c0] : SMALL_VAL;
    float obsB = (active && c1 < L) ? pred[(bT + 0) * L + c1] : SMALL_VAL;
    float mA = -3.4e38f, mB = -3.4e38f;
    #pragma unroll 8
    for (int k = 0; k < 64; k++) {
        float init = (k == 62) ? 0.0f : SMALL_VAL;   // b_s (start = L = 62)
        mA = fmaxf(mA, init + Tsh[k * 64 + c0]);
        mB = fmaxf(mB, init + Tsh[k * 64 + c1]);
    }
    float sA = 0.0f, sB = 0.0f;
    #pragma unroll 8
    for (int k = 0; k < 64; k++) {
        float init = (k == 62) ? 0.0f : SMALL_VAL;
        sA += __expf(init + Tsh[k * 64 + c0] - mA);
        sB += __expf(init + Tsh[k * 64 + c1] - mB);
    }
    float alA = obsA + mA + __logf(sA);
    float alB = obsB + mB + __logf(sB);
    float mm = fmaxf(alA, alB);
    #pragma unroll
    for (int o = 16; o > 0; o >>= 1)
        mm = fmaxf(mm, __shfl_xor_sync(FULLM, mm, o));
    const float m1 = mm;
    abuf[w][0][c0] = __expf(alA - m1);
    abuf[w][0][c1] = __expf(alB - m1);
    __syncwarp();

    // ---- main loop: S = n-1 steps; step q consumes pred row q+1 ----
    const int S = n - 1;
    int etot = 0;
    int cur  = 0;

    // 8-deep register prefetch pipeline per column.
    float buf0[8], buf1[8];
    #pragma unroll
    for (int j = 0; j < 8; j++) {
        buf0[j] = (active && j < S) ? pred[(bT + 1 + j) * L + c0] : SMALL_VAL;
        buf1[j] = (active && j < S && c1 < L) ? pred[(bT + 1 + j) * L + c1]
                                              : SMALL_VAL;
    }

    auto step_body = [&](int q, int j) {
        float P0 = __expf(buf0[j]);              // exp(SMALL) == 0 for pads
        float P1 = __expf(buf1[j]);
        int row = q + 9;
        float nf0 = SMALL_VAL, nf1 = SMALL_VAL;
        if (row <= S) {
            nf0 = pred[(bT + row) * L + c0];
            if (c1 < L) nf1 = pred[(bT + row) * L + c1];
        }

        const ulonglong2* a2 = (const ulonglong2*)(&abuf[w][cur][0]);
        ulonglong2 v0 = a2[0];
        int e = ((int)(v0.x >> 23) & 255) - 127;     // uniform across lanes
        e = max(-60, min(60, e));
        float scale = __int_as_float((127 - e) << 23);   // 2^{-e}, exact
        float ps0 = P0 * scale, ps1 = P1 * scale;

        unsigned long long A0[4], A1[4];
        A0[0] = fmul2(v0.x, E0[0]);  A1[0] = fmul2(v0.x, E1[0]);
        A0[1] = fmul2(v0.y, E0[1]);  A1[1] = fmul2(v0.y, E1[1]);
        {
            ulonglong2 v = a2[1];
            A0[2] = fmul2(v.x, E0[2]);  A1[2] = fmul2(v.x, E1[2]);
            A0[3] = fmul2(v.y, E0[3]);  A1[3] = fmul2(v.y, E1[3]);
        }
        #pragma unroll
        for (int q4 = 2; q4 < 16; q4++) {
            ulonglong2 v = a2[q4];
            int p0 = 2 * q4, p1 = 2 * q4 + 1;
            A0[p0 & 3] = ffma2(v.x, E0[p0], A0[p0 & 3]);
            A1[p0 & 3] = ffma2(v.x, E1[p0], A1[p0 & 3]);
            A0[p1 & 3] = ffma2(v.y, E0[p1], A0[p1 & 3]);
            A1[p1 & 3] = ffma2(v.y, E1[p1], A1[p1 & 3]);
        }
        unsigned long long r0 = fadd2(fadd2(A0[0], A0[1]), fadd2(A0[2], A0[3]));
        unsigned long long r1 = fadd2(fadd2(A1[0], A1[1]), fadd2(A1[2], A1[3]));
        float x0, y0, x1, y1;
        unpack2(r0, x0, y0);
        unpack2(r1, x1, y1);

        abuf[w][cur ^ 1][c0] = (x0 + y0) * ps0;
        abuf[w][cur ^ 1][c1] = (x1 + y1) * ps1;
        etot += e;
        buf0[j] = nf0;
        buf1[j] = nf1;
        cur ^= 1;
        __syncwarp();
    };

    const int full = S & ~7;
    for (int s0 = 0; s0 < full; s0 += 8) {
        #pragma unroll
        for (int j = 0; j < 8; j++) step_body(s0 + j, j);
    }
    #pragma unroll
    for (int j = 0; j < 8; j++) {       // remainder; n uniform per warp
        if (full + j < S) step_body(full + j, j);
    }

    // ---- final step (obs row n+1): only end column 63 (lane 31, c1) ----
    float s_res;
    {
        const ulonglong2* a2 = (const ulonglong2*)(&abuf[w][cur][0]);
        unsigned long long A1[4];
        {
            ulonglong2 v = a2[0];
            A1[0] = fmul2(v.x, E1[0]);
            A1[1] = fmul2(v.y, E1[1]);
        }
        {
            ulonglong2 v = a2[1];
            A1[2] = fmul2(v.x, E1[2]);
            A1[3] = fmul2(v.y, E1[3]);
        }
        #pragma unroll
        for (int q4 = 2; q4 < 16; q4++) {
            ulonglong2 v = a2[q4];
            int p0 = 2 * q4, p1 = 2 * q4 + 1;
            A1[p0 & 3] = ffma2(v.x, E1[p0], A1[p0 & 3]);
            A1[p1 & 3] = ffma2(v.y, E1[p1], A1[p1 & 3]);
        }
        unsigned long long r1 = fadd2(fadd2(A1[0], A1[1]), fadd2(A1[2], A1[3]));
        float x1, y1; unpack2(r1, x1, y1);
        float s = x1 + y1;
        s_res = m1 + (float)etot * 0.6931471805599453f + __logf(s);
        s_res = __shfl_sync(FULLM, s_res, 31);   // lane 31 owns column 63
    }

    // ---- gold path score: phased loads for MLP ----
    float rs = 0.0f;
    for (int base = 0; base < 512; base += 128) {
        if (base >= n) break;
        int   rr[4], rp[4];
        float gv[4];
        #pragma unroll
        for (int u = 0; u < 4; u++) {
            int t = base + l + u * 32;
            rr[u] = (t < n) ? ref[bT + t] : 0;
            rp[u] = (t >= 1 && t < n) ? ref[bT + t - 1] : 0;
        }
        #pragma unroll
        for (int u = 0; u < 4; u++) {
            int t = base + l + u * 32;
            gv[u] = (t < n) ? pred[(bT + t) * L + rr[u]] : 0.0f;
        }
        #pragma unroll
        for (int u = 0; u < 4; u++) {
            int t = base + l + u * 32;
            if (t < n) {
                rs += gv[u];
                if (t >= 1) rs += Tsh[rp[u] * 64 + rr[u]];
            }
        }
    }
    for (int t = l + 512; t < n; t += 32) {   // fallback for T > 512 (no-op here)
        int r = ref[bT + t];
        rs += pred[(bT + t) * L + r] + Tsh[ref[bT + t - 1] * 64 + r];
    }
    if (l == 0) {
        int r0 = ref[bT + 0];
        int rl = ref[bT + n - 1];
        rs += Tsh[62 * 64 + r0];          // start -> ref[0]
        rs += Tsh[rl * 64 + 63];          // ref[n-1] -> end
    }
    #pragma unroll
    for (int o = 16; o > 0; o >>= 1)      // deterministic butterfly
        rs += __shfl_xor_sync(FULLM, rs, o);

    if (active && l == 0) g_partials[b] = s_res - rs;

    // ---- last-finishing warp does the deterministic final reduction ----
    __threadfence();
    unsigned is_last = 0;
    if (l == 0) is_last = (atomicAdd(&g_done, 1) == nwarp - 1);
    is_last = __shfl_sync(FULLM, is_last, 0);
    if (is_last) {
        volatile float* gp = g_partials;
        float v = 0.0f;
        for (int i = l; i < B; i += 32) v += gp[i];   // fixed order per lane
        #pragma unroll
        for (int o = 16; o > 0; o >>= 1)
            v += __shfl_xor_sync(FULLM, v, o);        // deterministic butterfly
        if (l == 0) {
            out[0] = v;
            g_done = 0;                               // graph-replay reset
        }
    }
}

extern "C" void kernel_launch(void* const* d_in, const int* in_sizes, int n_in,
                              void* d_out, int out_size)
{
    const float* pred = (const float*)d_in[0];
    const int*   ref  = (const int*)d_in[1];
    const int*   seq  = (const int*)d_in[2];
    const float* trn  = (const float*)d_in[3];

    int B = in_sizes[2];                 // seq_len has B elements
    int T = in_sizes[1] / B;             // ref is B*T
    int L = in_sizes[0] / in_sizes[1];   // pred is B*T*L

    crf_perm_kernel<<<(B + 63) / 64, 64>>>(seq, B);
    crf_forward_kernel<<<(B + 3) / 4, 128>>>(pred, ref, seq, trn,
                                             (float*)d_out, B, T, L);
}

// round 11
// speedup vs baseline: 1.6181x; 1.1406x over previous
#include <cuda_runtime.h>
#include <cstdint>

#define SMALL_VAL (-1000.0f)
#define NSM 148
#define FULLM 0xffffffffu

// Allocation-free scratch.
__device__ float g_partials[8192];
__device__ int   g_perm[8192];
__device__ int   g_done;          // zero-init; last warp resets to 0 each run

// ---------- packed f32x2 helpers (Blackwell; ptxas won't auto-fuse) ----------
__device__ __forceinline__ unsigned long long pack2(float x, float y) {
    unsigned long long r;
    asm("mov.b64 %0, {%1, %2};" : "=l"(r) : "f"(x), "f"(y));
    return r;
}
__device__ __forceinline__ void unpack2(unsigned long long v, float& x, float& y) {
    asm("mov.b64 {%0, %1}, %2;" : "=f"(x), "=f"(y) : "l"(v));
}
__device__ __forceinline__ unsigned long long ffma2(unsigned long long a,
                                                    unsigned long long b,
                                                    unsigned long long c) {
    unsigned long long d;
    asm("fma.rn.f32x2 %0, %1, %2, %3;" : "=l"(d) : "l"(a), "l"(b), "l"(c));
    return d;
}
__device__ __forceinline__ unsigned long long fmul2(unsigned long long a,
                                                    unsigned long long b) {
    unsigned long long d;
    asm("mul.rn.f32x2 %0, %1, %2;" : "=l"(d) : "l"(a), "l"(b));
    return d;
}
__device__ __forceinline__ unsigned long long fadd2(unsigned long long a,
                                                    unsigned long long b) {
    unsigned long long d;
    asm("add.rn.f32x2 %0, %1, %2;" : "=l"(d) : "l"(a), "l"(b));
    return d;
}

// ============================================================================
// Scheduling permutation: g_perm[rank] = batch, rank by seq_len descending
// (stable). The forward kernel maps warp slots -> ranks with a snake over
// the 148 co-residence columns (bids s and s+148 share an SM), equalizing
// per-SM total work. Scheduling only; reduced value is order-independent.
// ============================================================================
__global__ void crf_perm_kernel(const int* __restrict__ seq_len, int B)
{
    __shared__ int ns[4096];
    const bool use_sh = (B <= 4096);
    if (use_sh) {
        for (int i = threadIdx.x; i < B; i += blockDim.x) ns[i] = seq_len[i];
        __syncthreads();
    }
    int i = blockIdx.x * blockDim.x + threadIdx.x;
    if (i >= B) return;
    int ni = use_sh ? ns[i] : seq_len[i];
    int r = 0;
    #pragma unroll 4
    for (int j = 0; j < B; j++) {
        int nj = use_sh ? ns[j] : seq_len[j];
        r += (nj > ni) || (nj == ni && j < i);
    }
    g_perm[r] = i;
}

// ============================================================================
// Forward CRF: 128-thread blocks = 4 INDEPENDENT warps, each one batch
// element. Grid = 2*NSM: bids s and s+NSM co-locate (bid%NSM placement), so
// every SM hosts exactly 8 warps (2 per SMSP). Warp slot (bid,w) takes
//   row = (bid/NSM)*4 + w, col = bid%NSM,
//   rank = row*NSM + (row odd ? NSM-1-col : col)   [snake -> per-SM balance]
// Slots with rank >= B idle (they hold the shortest ranks' slots anyway).
//
// Per warp, lane l owns columns c0 = l, c1 = l + 32.
// Linear-domain recursion:
//   a_t[k'] = (sum_k a_{t-1}[k] * E[k][k']) * exp(obs_t[k']) * 2^{-e_t}
// E = exp(transitions): 2 columns x 32 packed f32x2 in registers (rows 62/63
// are exp(-10000) = 0 automatically). a double-buffered per warp in shared,
// 16 broadcast LDS.128 per step shared by both columns -> 64 ffma2 per
// ~110 warp-instructions. Rescale exponent from a_prev[0] (uniform), exact
// integer accumulation, folded in at the end as etot*ln2. Step 1 in exact
// log domain. pred rows software-prefetched 8 steps ahead.
// Last-finishing warp does the deterministic final reduction.
// ============================================================================
__global__ void __launch_bounds__(128, 2) crf_forward_kernel(
    const float* __restrict__ pred,
    const int*   __restrict__ ref,
    const int*   __restrict__ seq_len,
    const float* __restrict__ trans,
    float* __restrict__ out,
    int B, int T, int L)
{
    __shared__ float Tsh[64 * 64];
    __shared__ __align__(16) float abuf[4][2][64];   // per-warp double buffer

    const int w  = threadIdx.x >> 5;     // warp in block = SMSP
    const int l  = threadIdx.x & 31;
    const int c0 = l;                    // always < L (= 62)
    const int c1 = l + 32;               // 32..63; end state = 63

    // snake rank assignment over co-residence columns
    const int col  = blockIdx.x % NSM;
    const int row  = (blockIdx.x / NSM) * 4 + w;
    const int rank = row * NSM + ((row & 1) ? (NSM - 1 - col) : col);

    // ---- load transitions (K = L+2 = 64) cooperatively, one block sync ----
    {
        const float4* src = (const float4*)trans;
        float4* dst = (float4*)Tsh;
        for (int i = threadIdx.x; i < 1024; i += 128) dst[i] = src[i];
    }
    __syncthreads();

    const bool active = (rank < B);
    const int b = active ? g_perm[rank] : 0;
    const int n = active ? seq_len[b] : 1;     // in [1, T]
    const size_t bT = (size_t)b * T;

    // ---- E columns c0, c1 in registers (32 k-pairs each) ----
    unsigned long long E0[32], E1[32];
    #pragma unroll
    for (int p = 0; p < 32; p++) {
        E0[p] = pack2(__expf(Tsh[(2 * p) * 64 + c0]),
                      __expf(Tsh[(2 * p + 1) * 64 + c0]));
        E1[p] = pack2(__expf(Tsh[(2 * p) * 64 + c1]),
                      __expf(Tsh[(2 * p + 1) * 64 + c1]));
    }

    // ---- step 1 (obs row 1 = pred row 0), exact log-domain LSE ----
    float obsA = active ? pred[(bT + 0) * L + c0] : SMALL_VAL;
    float obsB = (active && c1 < L) ? pred[(bT + 0) * L + c1] : SMALL_VAL;
    float mA = -3.4e38f, mB = -3.4e38f;
    #pragma unroll 8
    for (int k = 0; k < 64; k++) {
        float init = (k == 62) ? 0.0f : SMALL_VAL;   // b_s (start = L = 62)
        mA = fmaxf(mA, init + Tsh[k * 64 + c0]);
        mB = fmaxf(mB, init + Tsh[k * 64 + c1]);
    }
    float sA = 0.0f, sB = 0.0f;
    #pragma unroll 8
    for (int k = 0; k < 64; k++) {
        float init = (k == 62) ? 0.0f : SMALL_VAL;
        sA += __expf(init + Tsh[k * 64 + c0] - mA);
        sB += __expf(init + Tsh[k * 64 + c1] - mB);
    }
    float alA = obsA + mA + __logf(sA);
    float alB = obsB + mB + __logf(sB);
    float mm = fmaxf(alA, alB);
    #pragma unroll
    for (int o = 16; o > 0; o >>= 1)
        mm = fmaxf(mm, __shfl_xor_sync(FULLM, mm, o));
    const float m1 = mm;
    abuf[w][0][c0] = __expf(alA - m1);
    abuf[w][0][c1] = __expf(alB - m1);
    __syncwarp();

    // ---- main loop: S = n-1 steps; step q consumes pred row q+1 ----
    const int S = n - 1;
    int etot = 0;
    int cur  = 0;

    // 8-deep register prefetch pipeline per column.
    float buf0[8], buf1[8];
    #pragma unroll
    for (int j = 0; j < 8; j++) {
        buf0[j] = (active && j < S) ? pred[(bT + 1 + j) * L + c0] : SMALL_VAL;
        buf1[j] = (active && j < S && c1 < L) ? pred[(bT + 1 + j) * L + c1]
                                              : SMALL_VAL;
    }

    auto step_body = [&](int q, int j) {
        float P0 = __expf(buf0[j]);              // exp(SMALL) == 0 for pads
        float P1 = __expf(buf1[j]);
        int row_ = q + 9;
        float nf0 = SMALL_VAL, nf1 = SMALL_VAL;
        if (row_ <= S) {
            nf0 = pred[(bT + row_) * L + c0];
            if (c1 < L) nf1 = pred[(bT + row_) * L + c1];
        }

        const ulonglong2* a2 = (const ulonglong2*)(&abuf[w][cur][0]);
        ulonglong2 v0 = a2[0];
        int e = ((int)(v0.x >> 23) & 255) - 127;     // uniform across lanes
        e = max(-60, min(60, e));
        float scale = __int_as_float((127 - e) << 23);   // 2^{-e}, exact
        float ps0 = P0 * scale, ps1 = P1 * scale;

        unsigned long long A0[4], A1[4];
        A0[0] = fmul2(v0.x, E0[0]);  A1[0] = fmul2(v0.x, E1[0]);
        A0[1] = fmul2(v0.y, E0[1]);  A1[1] = fmul2(v0.y, E1[1]);
        {
            ulonglong2 v = a2[1];
            A0[2] = fmul2(v.x, E0[2]);  A1[2] = fmul2(v.x, E1[2]);
            A0[3] = fmul2(v.y, E0[3]);  A1[3] = fmul2(v.y, E1[3]);
        }
        #pragma unroll
        for (int q4 = 2; q4 < 16; q4++) {
            ulonglong2 v = a2[q4];
            int p0 = 2 * q4, p1 = 2 * q4 + 1;
            A0[p0 & 3] = ffma2(v.x, E0[p0], A0[p0 & 3]);
            A1[p0 & 3] = ffma2(v.x, E1[p0], A1[p0 & 3]);
            A0[p1 & 3] = ffma2(v.y, E0[p1], A0[p1 & 3]);
            A1[p1 & 3] = ffma2(v.y, E1[p1], A1[p1 & 3]);
        }
        unsigned long long r0 = fadd2(fadd2(A0[0], A0[1]), fadd2(A0[2], A0[3]));
        unsigned long long r1 = fadd2(fadd2(A1[0], A1[1]), fadd2(A1[2], A1[3]));
        float x0, y0, x1, y1;
        unpack2(r0, x0, y0);
        unpack2(r1, x1, y1);

        abuf[w][cur ^ 1][c0] = (x0 + y0) * ps0;
        abuf[w][cur ^ 1][c1] = (x1 + y1) * ps1;
        etot += e;
        buf0[j] = nf0;
        buf1[j] = nf1;
        cur ^= 1;
        __syncwarp();
    };

    const int full = S & ~7;
    for (int s0 = 0; s0 < full; s0 += 8) {
        #pragma unroll
        for (int j = 0; j < 8; j++) step_body(s0 + j, j);
    }
    #pragma unroll
    for (int j = 0; j < 8; j++) {       // remainder; n uniform per warp
        if (full + j < S) step_body(full + j, j);
    }

    // ---- final step (obs row n+1): only end column 63 (lane 31, c1) ----
    float s_res;
    {
        const ulonglong2* a2 = (const ulonglong2*)(&abuf[w][cur][0]);
        unsigned long long A1[4];
        {
            ulonglong2 v = a2[0];
            A1[0] = fmul2(v.x, E1[0]);
            A1[1] = fmul2(v.y, E1[1]);
        }
        {
            ulonglong2 v = a2[1];
            A1[2] = fmul2(v.x, E1[2]);
            A1[3] = fmul2(v.y, E1[3]);
        }
        #pragma unroll
        for (int q4 = 2; q4 < 16; q4++) {
            ulonglong2 v = a2[q4];
            int p0 = 2 * q4, p1 = 2 * q4 + 1;
            A1[p0 & 3] = ffma2(v.x, E1[p0], A1[p0 & 3]);
            A1[p1 & 3] = ffma2(v.y, E1[p1], A1[p1 & 3]);
        }
        unsigned long long r1 = fadd2(fadd2(A1[0], A1[1]), fadd2(A1[2], A1[3]));
        float x1, y1; unpack2(r1, x1, y1);
        float s = x1 + y1;
        s_res = m1 + (float)etot * 0.6931471805599453f + __logf(s);
        s_res = __shfl_sync(FULLM, s_res, 31);   // lane 31 owns column 63
    }

    // ---- gold path score: phased loads for MLP ----
    float rs = 0.0f;
    for (int base = 0; base < 512; base += 128) {
        if (base >= n) break;
        int   rr[4], rp[4];
        float gv[4];
        #pragma unroll
        for (int u = 0; u < 4; u++) {
            int t = base + l + u * 32;
            rr[u] = (t < n) ? ref[bT + t] : 0;
            rp[u] = (t >= 1 && t < n) ? ref[bT + t - 1] : 0;
        }
        #pragma unroll
        for (int u = 0; u < 4; u++) {
            int t = base + l + u * 32;
            gv[u] = (t < n) ? pred[(bT + t) * L + rr[u]] : 0.0f;
        }
        #pragma unroll
        for (int u = 0; u < 4; u++) {
            int t = base + l + u * 32;
            if (t < n) {
                rs += gv[u];
                if (t >= 1) rs += Tsh[rp[u] * 64 + rr[u]];
            }
        }
    }
    for (int t = l + 512; t < n; t += 32) {   // fallback for T > 512 (no-op here)
        int r = ref[bT + t];
        rs += pred[(bT + t) * L + r] + Tsh[ref[bT + t - 1] * 64 + r];
    }
    if (l == 0) {
        int r0 = ref[bT + 0];
        int rl = ref[bT + n - 1];
        rs += Tsh[62 * 64 + r0];          // start -> ref[0]
        rs += Tsh[rl * 64 + 63];          // ref[n-1] -> end
    }
    #pragma unroll
    for (int o = 16; o > 0; o >>= 1)      // deterministic butterfly
        rs += __shfl_xor_sync(FULLM, rs, o);

    if (active && l == 0) g_partials[b] = s_res - rs;

    // ---- last-finishing active warp does the deterministic reduction ----
    if (active) {
        __threadfence();
        unsigned is_last = 0;
        if (l == 0) is_last = (atomicAdd(&g_done, 1) == B - 1);
        is_last = __shfl_sync(FULLM, is_last, 0);
        if (is_last) {
            volatile float* gp = g_partials;
            float v = 0.0f;
            for (int i = l; i < B; i += 32) v += gp[i];   // fixed order per lane
            #pragma unroll
            for (int o = 16; o > 0; o >>= 1)
                v += __shfl_xor_sync(FULLM, v, o);        // deterministic
            if (l == 0) {
                out[0] = v;
                g_done = 0;                               // graph-replay reset
            }
        }
    }
}

extern "C" void kernel_launch(void* const* d_in, const int* in_sizes, int n_in,
                              void* d_out, int out_size)
{
    const float* pred = (const float*)d_in[0];
    const int*   ref  = (const int*)d_in[1];
    const int*   seq  = (const int*)d_in[2];
    const float* trn  = (const float*)d_in[3];

    int B = in_sizes[2];                 // seq_len has B elements
    int T = in_sizes[1] / B;             // ref is B*T
    int L = in_sizes[0] / in_sizes[1];   // pred is B*T*L

    // grid: multiple of NSM with >= B warp slots, so every SM hosts the same
    // number of blocks and the snake covers all batches.
    int rows4  = (B + 4 * NSM - 1) / (4 * NSM);      // block-rows needed
    int nblk   = rows4 * NSM;                        // 296 for B=1024
    crf_perm_kernel<<<(B + 63) / 64, 64>>>(seq, B);
    crf_forward_kernel<<<nblk, 128>>>(pred, ref, seq, trn,
                                      (float*)d_out, B, T, L);
}